// round 4
// baseline (speedup 1.0000x reference)
#include <cuda_runtime.h>
#include <cstdint>

// ---------------------------------------------------------------------------
// WindowAttention (Swin) — fp32, FFMA2 (fma.rn.f32x2) packed math
//   R3: identical to R2 (dup-A smem, double-buffered, 1 barrier/ktile) with
//       __launch_bounds__(256,2) pinning the 2-CTA/SM operating point.
// ---------------------------------------------------------------------------

#define M_TOTAL   100352          // 2048*49
#define KDIM      512
#define NQKV      1536
#define NPROJ     512
#define HEADS     16
#define NTOK      49
#define HD        32
#define SCALE_Q   0.17677669529663687f   // 32^-0.5

__device__ float g_q[2048u * 16 * 49 * 32];     // [B*H][49][32]
__device__ float g_k[2048u * 16 * 49 * 32];
__device__ float g_v[2048u * 16 * 49 * 32];
__device__ float g_att[2048u * 49 * 512];       // [B][49][C]
__device__ float g_hbias[16 * 49 * 49];         // [H][49][49]

// ---- packed f32x2 helpers --------------------------------------------------
__device__ __forceinline__ unsigned long long ffma2(unsigned long long a,
                                                    unsigned long long b,
                                                    unsigned long long c) {
    unsigned long long d;
    asm("fma.rn.f32x2 %0, %1, %2, %3;" : "=l"(d) : "l"(a), "l"(b), "l"(c));
    return d;
}
__device__ __forceinline__ unsigned long long pack2(float x, float y) {
    unsigned long long d;
    asm("mov.b64 %0, {%1, %2};" : "=l"(d) : "f"(x), "f"(y));
    return d;
}
__device__ __forceinline__ float lo32(unsigned long long v) {
    return __uint_as_float((unsigned)(v & 0xffffffffull));
}
__device__ __forceinline__ float hi32(unsigned long long v) {
    return __uint_as_float((unsigned)(v >> 32));
}

// ---------------------------------------------------------------------------
// 1. bias gather
// ---------------------------------------------------------------------------
__global__ void bias_kernel(const float* __restrict__ bt, const int* __restrict__ ri) {
    int idx = blockIdx.x * 256 + threadIdx.x;
    if (idx < 16 * 2401) {
        int h  = idx / 2401;
        int ij = idx - h * 2401;
        g_hbias[idx] = bt[ri[ij] * 16 + h];
    }
}

// ---------------------------------------------------------------------------
// 2/4. GEMM  C[M,N] = A[M,512] @ W[N,512]^T + bias
//   BM=BN=128, BK=16, 256 thr, 8x8 micro-tile (8 x 4 f32x2 accumulators)
//   As stored DUPLICATED: As[buf][k][2m] = As[buf][k][2m+1] = A[m][k]
//   Double-buffered: one __syncthreads per ktile.
// ---------------------------------------------------------------------------
template <int MODE>
__global__ __launch_bounds__(256, 2) void gemm_kernel(const float* __restrict__ Ain,
                                                      const float* __restrict__ W,
                                                      const float* __restrict__ bias,
                                                      float* __restrict__ Cout) {
    __shared__ __align__(16) float As[2][16][256];   // dup-A, row = 1024B
    __shared__ __align__(16) float Bs[2][16][128];   // row = 512B
    // total = 32768 + 16384 = 49152 B = 48KB exactly

    const float* A = (MODE == 1) ? (const float*)g_att : Ain;

    const int tid = threadIdx.x;
    const int m0  = blockIdx.y * 128;
    const int n0  = blockIdx.x * 128;

    // loader mapping: r0 = row (0..127), c0/c1 = float4 index within 16-k strip
    const int r0 = tid >> 1;
    const int c0 = (tid & 1) * 2;
    const int c1 = c0 + 1;

    const float* ap0 = A + (size_t)(m0 + r0) * KDIM + c0 * 4;
    const float* ap1 = A + (size_t)(m0 + r0) * KDIM + c1 * 4;
    const float* bp0 = W + (size_t)(n0 + r0) * KDIM + c0 * 4;
    const float* bp1 = W + (size_t)(n0 + r0) * KDIM + c1 * 4;

    const int m_off = (tid >> 4) * 8;
    const int n_off = (tid & 15) * 8;

    unsigned long long c[8][4];
#pragma unroll
    for (int i = 0; i < 8; i++)
#pragma unroll
        for (int j = 0; j < 4; j++) c[i][j] = 0ull;

    float4 ra0 = *(const float4*)(ap0);
    float4 ra1 = *(const float4*)(ap1);
    float4 rb0 = *(const float4*)(bp0);
    float4 rb1 = *(const float4*)(bp1);

#define STORE_TILES(BUF)                                                                \
    do {                                                                                \
        float2 d;                                                                       \
        d.x = d.y = ra0.x; *(float2*)&As[BUF][c0 * 4 + 0][2 * r0] = d;                  \
        d.x = d.y = ra0.y; *(float2*)&As[BUF][c0 * 4 + 1][2 * r0] = d;                  \
        d.x = d.y = ra0.z; *(float2*)&As[BUF][c0 * 4 + 2][2 * r0] = d;                  \
        d.x = d.y = ra0.w; *(float2*)&As[BUF][c0 * 4 + 3][2 * r0] = d;                  \
        d.x = d.y = ra1.x; *(float2*)&As[BUF][c1 * 4 + 0][2 * r0] = d;                  \
        d.x = d.y = ra1.y; *(float2*)&As[BUF][c1 * 4 + 1][2 * r0] = d;                  \
        d.x = d.y = ra1.z; *(float2*)&As[BUF][c1 * 4 + 2][2 * r0] = d;                  \
        d.x = d.y = ra1.w; *(float2*)&As[BUF][c1 * 4 + 3][2 * r0] = d;                  \
        Bs[BUF][c0 * 4 + 0][r0] = rb0.x; Bs[BUF][c0 * 4 + 1][r0] = rb0.y;               \
        Bs[BUF][c0 * 4 + 2][r0] = rb0.z; Bs[BUF][c0 * 4 + 3][r0] = rb0.w;               \
        Bs[BUF][c1 * 4 + 0][r0] = rb1.x; Bs[BUF][c1 * 4 + 1][r0] = rb1.y;               \
        Bs[BUF][c1 * 4 + 2][r0] = rb1.z; Bs[BUF][c1 * 4 + 3][r0] = rb1.w;               \
    } while (0)

    STORE_TILES(0);
    __syncthreads();

    const int KTILES = KDIM / 16;   // 32
    for (int kt = 0; kt < KTILES; kt++) {
        const int buf = kt & 1;
        if (kt < KTILES - 1) {
            int ko = (kt + 1) * 16;
            ra0 = *(const float4*)(ap0 + ko);
            ra1 = *(const float4*)(ap1 + ko);
            rb0 = *(const float4*)(bp0 + ko);
            rb1 = *(const float4*)(bp1 + ko);
        }
#pragma unroll
        for (int k = 0; k < 16; k++) {
            ulonglong2 a01 = *(const ulonglong2*)&As[buf][k][2 * m_off];
            ulonglong2 a23 = *(const ulonglong2*)&As[buf][k][2 * m_off + 4];
            ulonglong2 a45 = *(const ulonglong2*)&As[buf][k][2 * m_off + 8];
            ulonglong2 a67 = *(const ulonglong2*)&As[buf][k][2 * m_off + 12];
            ulonglong2 b0  = *(const ulonglong2*)&Bs[buf][k][n_off];
            ulonglong2 b1  = *(const ulonglong2*)&Bs[buf][k][n_off + 4];
            unsigned long long av[8] = {a01.x, a01.y, a23.x, a23.y,
                                        a45.x, a45.y, a67.x, a67.y};
#pragma unroll
            for (int i = 0; i < 8; i++) {
                c[i][0] = ffma2(av[i], b0.x, c[i][0]);
                c[i][1] = ffma2(av[i], b0.y, c[i][1]);
                c[i][2] = ffma2(av[i], b1.x, c[i][2]);
                c[i][3] = ffma2(av[i], b1.y, c[i][3]);
            }
        }
        if (kt < KTILES - 1) {
            STORE_TILES(buf ^ 1);
            __syncthreads();
        }
    }
#undef STORE_TILES

    // epilogue
#pragma unroll
    for (int i = 0; i < 8; i++) {
        int m = m0 + m_off + i;
        int b = 0, tok = 0;
        if (MODE == 0) { b = m / NTOK; tok = m - b * NTOK; }
#pragma unroll
        for (int jp = 0; jp < 4; jp++) {
            int n = n0 + n_off + jp * 2;                 // n even; n,n+1 same (s,h)
            float v0 = lo32(c[i][jp]) + bias[n];
            float v1 = hi32(c[i][jp]) + bias[n + 1];
            if (MODE == 0) {
                int s = n >> 9;
                int h = (n >> 5) & 15;
                int d = n & 31;
                float* dst = (s == 0) ? g_q : (s == 1) ? g_k : g_v;
                float sc   = (s == 0) ? SCALE_Q : 1.0f;
                size_t base = (((size_t)b * HEADS + h) * NTOK + tok) * HD + d;
                dst[base]     = v0 * sc;
                dst[base + 1] = v1 * sc;
            } else {
                Cout[(size_t)m * NPROJ + n]     = v0;
                Cout[(size_t)m * NPROJ + n + 1] = v1;
            }
        }
    }
}

// ---------------------------------------------------------------------------
// 3. attention: one CTA per (b,h); thread i owns query row i (i<49).
// ---------------------------------------------------------------------------
__global__ __launch_bounds__(64) void attn_kernel(const float* __restrict__ mask) {
    __shared__ __align__(16) float ks[NTOK * HD];
    __shared__ __align__(16) float vs[NTOK * HD];

    int bh = blockIdx.x;          // b*16 + h
    int b  = bh >> 4;
    int h  = bh & 15;
    int w  = b & 63;              // window index within image

    size_t base = (size_t)bh * (NTOK * HD);
    {
        const float4* kg = (const float4*)(g_k + base);
        const float4* vg = (const float4*)(g_v + base);
        float4* ks4 = (float4*)ks;
        float4* vs4 = (float4*)vs;
        for (int t = threadIdx.x; t < (NTOK * HD) / 4; t += 64) {
            ks4[t] = kg[t];
            vs4[t] = vg[t];
        }
    }
    __syncthreads();

    int i = threadIdx.x;
    if (i >= NTOK) return;

    unsigned long long q2[16];    // 32 q floats as 16 f32x2
    {
        const ulonglong2* qp = (const ulonglong2*)(g_q + base + (size_t)i * HD);
#pragma unroll
        for (int t = 0; t < 8; t++) {
            ulonglong2 u = qp[t];
            q2[2 * t]     = u.x;
            q2[2 * t + 1] = u.y;
        }
    }

    const float* bb = g_hbias + (h * (NTOK * NTOK) + i * NTOK);
    const float* mm = mask + ((size_t)w * NTOK + i) * NTOK;

    float s[NTOK];
#pragma unroll
    for (int j = 0; j < NTOK; j++) {
        const ulonglong2* kr = (const ulonglong2*)(ks + j * HD);
        unsigned long long a0 = 0, a1 = 0, a2 = 0, a3 = 0;
#pragma unroll
        for (int t = 0; t < 4; t++) {
            ulonglong2 k0 = kr[2 * t];
            ulonglong2 k1 = kr[2 * t + 1];
            a0 = ffma2(q2[4 * t + 0], k0.x, a0);
            a1 = ffma2(q2[4 * t + 1], k0.y, a1);
            a2 = ffma2(q2[4 * t + 2], k1.x, a2);
            a3 = ffma2(q2[4 * t + 3], k1.y, a3);
        }
        float r = (lo32(a0) + hi32(a0)) + (lo32(a1) + hi32(a1)) +
                  (lo32(a2) + hi32(a2)) + (lo32(a3) + hi32(a3));
        s[j] = r + __ldg(bb + j) + __ldg(mm + j);
    }

    float mx = s[0];
#pragma unroll
    for (int j = 1; j < NTOK; j++) mx = fmaxf(mx, s[j]);
    float sum = 0.0f;
#pragma unroll
    for (int j = 0; j < NTOK; j++) {
        float e = __expf(s[j] - mx);
        s[j] = e;
        sum += e;
    }
    float inv = 1.0f / sum;

    unsigned long long o2[16];
#pragma unroll
    for (int t = 0; t < 16; t++) o2[t] = 0ull;
#pragma unroll
    for (int j = 0; j < NTOK; j++) {
        unsigned long long pp = pack2(s[j], s[j]);
        const ulonglong2* vr = (const ulonglong2*)(vs + j * HD);
#pragma unroll
        for (int t = 0; t < 8; t++) {
            ulonglong2 vv = vr[t];
            o2[2 * t]     = ffma2(pp, vv.x, o2[2 * t]);
            o2[2 * t + 1] = ffma2(pp, vv.y, o2[2 * t + 1]);
        }
    }

    float* og = g_att + ((size_t)(b * NTOK + i)) * 512 + h * HD;
#pragma unroll
    for (int t = 0; t < 8; t++) {
        float4 f;
        f.x = lo32(o2[2 * t]) * inv;
        f.y = hi32(o2[2 * t]) * inv;
        f.z = lo32(o2[2 * t + 1]) * inv;
        f.w = hi32(o2[2 * t + 1]) * inv;
        *(float4*)(og + 4 * t) = f;
    }
}

// ---------------------------------------------------------------------------
extern "C" void kernel_launch(void* const* d_in, const int* in_sizes, int n_in,
                              void* d_out, int out_size) {
    const float* x          = (const float*)d_in[0];
    const float* w_qkv      = (const float*)d_in[1];
    const float* b_qkv      = (const float*)d_in[2];
    const float* w_proj     = (const float*)d_in[3];
    const float* b_proj     = (const float*)d_in[4];
    const float* bias_table = (const float*)d_in[5];
    const int*   rel_index  = (const int*)d_in[6];
    const float* mask       = (const float*)d_in[7];
    float* out = (float*)d_out;

    bias_kernel<<<(16 * 2401 + 255) / 256, 256>>>(bias_table, rel_index);
    gemm_kernel<0><<<dim3(NQKV / 128, M_TOTAL / 128), 256>>>(x, w_qkv, b_qkv, nullptr);
    attn_kernel<<<2048 * 16, 64>>>(mask);
    gemm_kernel<1><<<dim3(NPROJ / 128, M_TOTAL / 128), 256>>>(nullptr, w_proj, b_proj, out);
}

// round 8
// speedup vs baseline: 2.7154x; 2.7154x over previous
#include <cuda_runtime.h>
#include <cuda_bf16.h>
#include <cstdint>

// ---------------------------------------------------------------------------
// WindowAttention (Swin) — R7: mma.sync bf16 3-term-split GEMMs (plain sm_103
//   PTX — tcgen05 is 'a'-only and this harness builds compute_103 PTX).
//   GEMM: CTA 128x128, warp 64x32, m16n8k16 HMMA, K-chunk 64,
//         D = Ah*Bh + Ah*Bl + Al*Bh accumulated in fp32 regs.
// ---------------------------------------------------------------------------

#define M_TOTAL   100352          // 2048*49
#define KDIM      512
#define NQKV      1536
#define NPROJ     512
#define HEADS     16
#define NTOK      49
#define HD        32
#define SCALE_Q   0.17677669529663687f   // 32^-0.5

// smem tile: 128 rows x (64 data + 8 pad) bf16 = 144B rows -> conflict-free ldmatrix
#define ROWB      144
#define TILEB     (128 * ROWB)    // 18432
#define SMEM_BYTES (4 * TILEB)    // Ah | Al | Bh | Bl = 73728

__device__ float g_q[2048u * 16 * 49 * 32];     // [B*H][49][32]
__device__ float g_k[2048u * 16 * 49 * 32];
__device__ float g_v[2048u * 16 * 49 * 32];
__device__ float g_att[2048u * 49 * 512];       // [B][49][C]
__device__ float g_hbias[16 * 49 * 49];         // [H][49][49]

// ---- helpers ---------------------------------------------------------------
__device__ __forceinline__ uint32_t smem_u32(const void* p) {
    uint32_t a;
    asm("{ .reg .u64 t; cvta.to.shared.u64 t, %1; cvt.u32.u64 %0, t; }"
        : "=r"(a) : "l"(p));
    return a;
}
// pack two fp32 -> bf16x2 (lo = a, hi = b), round-to-nearest
__device__ __forceinline__ uint32_t cvt2bf(float a, float b) {
    uint32_t r;
    asm("cvt.rn.bf16x2.f32 %0, %1, %2;" : "=r"(r) : "f"(b), "f"(a));
    return r;
}
__device__ __forceinline__ void ldsm4(uint32_t* r, uint32_t addr) {
    asm volatile("ldmatrix.sync.aligned.m8n8.x4.shared.b16 {%0,%1,%2,%3}, [%4];"
                 : "=r"(r[0]), "=r"(r[1]), "=r"(r[2]), "=r"(r[3]) : "r"(addr));
}
__device__ __forceinline__ void ldsm2(uint32_t* r, uint32_t addr) {
    asm volatile("ldmatrix.sync.aligned.m8n8.x2.shared.b16 {%0,%1}, [%2];"
                 : "=r"(r[0]), "=r"(r[1]) : "r"(addr));
}
__device__ __forceinline__ void mma_bf16(float* d, const uint32_t* a, const uint32_t* b) {
    asm volatile("mma.sync.aligned.m16n8k16.row.col.f32.bf16.bf16.f32 "
                 "{%0,%1,%2,%3}, {%4,%5,%6,%7}, {%8,%9}, {%0,%1,%2,%3};"
                 : "+f"(d[0]), "+f"(d[1]), "+f"(d[2]), "+f"(d[3])
                 : "r"(a[0]), "r"(a[1]), "r"(a[2]), "r"(a[3]), "r"(b[0]), "r"(b[1]));
}

// ---- packed f32x2 helpers (attention) --------------------------------------
__device__ __forceinline__ unsigned long long ffma2(unsigned long long a,
                                                    unsigned long long b,
                                                    unsigned long long c) {
    unsigned long long d;
    asm("fma.rn.f32x2 %0, %1, %2, %3;" : "=l"(d) : "l"(a), "l"(b), "l"(c));
    return d;
}
__device__ __forceinline__ unsigned long long pack2(float x, float y) {
    unsigned long long d;
    asm("mov.b64 %0, {%1, %2};" : "=l"(d) : "f"(x), "f"(y));
    return d;
}
__device__ __forceinline__ float lo32(unsigned long long v) {
    return __uint_as_float((unsigned)(v & 0xffffffffull));
}
__device__ __forceinline__ float hi32(unsigned long long v) {
    return __uint_as_float((unsigned)(v >> 32));
}

// ---------------------------------------------------------------------------
// 1. bias gather
// ---------------------------------------------------------------------------
__global__ void bias_kernel(const float* __restrict__ bt, const int* __restrict__ ri) {
    int idx = blockIdx.x * 256 + threadIdx.x;
    if (idx < 16 * 2401) {
        int h  = idx / 2401;
        int ij = idx - h * 2401;
        g_hbias[idx] = bt[ri[ij] * 16 + h];
    }
}

// ---------------------------------------------------------------------------
// tile loader: fp32 [128 rows x 64 k] -> bf16 hi/lo tiles (144B padded rows).
// 256 threads x 4 segments (segment = 8 elems = 16B bf16 per tile).
// hi = rn(v); lo = rn(v - f32(hi));  f32(bf16) is a 16-bit shift.
// ---------------------------------------------------------------------------
__device__ __forceinline__ void load_conv(const float* __restrict__ src, int row0,
                                          int k0, char* hi_t, char* lo_t, int tid) {
#pragma unroll
    for (int i = 0; i < 4; i++) {
        int s   = tid + i * 256;
        int row = s >> 3;
        int cs  = s & 7;
        const float* g = src + (size_t)(row0 + row) * KDIM + k0 + cs * 8;
        float4 f0 = *(const float4*)g;
        float4 f1 = *(const float4*)(g + 4);
        float v[8] = {f0.x, f0.y, f0.z, f0.w, f1.x, f1.y, f1.z, f1.w};
        uint32_t hi[4], lo[4];
#pragma unroll
        for (int j = 0; j < 4; j++) {
            uint32_t hp = cvt2bf(v[2 * j], v[2 * j + 1]);
            float h0 = __uint_as_float(hp << 16);
            float h1 = __uint_as_float(hp & 0xFFFF0000u);
            hi[j] = hp;
            lo[j] = cvt2bf(v[2 * j] - h0, v[2 * j + 1] - h1);
        }
        int byte = row * ROWB + cs * 16;
        *(uint4*)(hi_t + byte) = make_uint4(hi[0], hi[1], hi[2], hi[3]);
        *(uint4*)(lo_t + byte) = make_uint4(lo[0], lo[1], lo[2], lo[3]);
    }
}

// ---------------------------------------------------------------------------
// 2/4. HMMA GEMM  C[M,N] = A[M,512] @ W[N,512]^T + bias
//   MODE 0: A = x,     N=1536, scatter epilogue into g_q/g_k/g_v (q scaled)
//   MODE 1: A = g_att, N=512,  plain epilogue into Cout
// ---------------------------------------------------------------------------
template <int MODE>
__global__ __launch_bounds__(256) void gemm_mma(const float* __restrict__ Ain,
                                                const float* __restrict__ W,
                                                const float* __restrict__ bias,
                                                float* __restrict__ Cout) {
    extern __shared__ char sm[];
    char* smAh = sm;
    char* smAl = sm + TILEB;
    char* smBh = sm + 2 * TILEB;
    char* smBl = sm + 3 * TILEB;

    const float* A = (MODE == 1) ? (const float*)g_att : Ain;

    const int tid  = threadIdx.x;
    const int wid  = tid >> 5;
    const int lane = tid & 31;
    const int m0   = blockIdx.y * 128;
    const int n0   = blockIdx.x * 128;
    const int m_w  = (wid & 1) * 64;      // warp M offset in CTA tile
    const int n_w  = (wid >> 1) * 32;     // warp N offset

    const uint32_t smb = smem_u32(sm);
    // per-lane ldmatrix row/col (bytes)
    const uint32_t aOff = (uint32_t)(lane & 15) * ROWB + (uint32_t)(lane >> 4) * 16;
    const uint32_t bOff = (uint32_t)(lane & 7) * ROWB + (uint32_t)((lane >> 3) & 1) * 16;

    float c[4][4][4];
#pragma unroll
    for (int mi = 0; mi < 4; mi++)
#pragma unroll
        for (int ni = 0; ni < 4; ni++)
#pragma unroll
            for (int f = 0; f < 4; f++) c[mi][ni][f] = 0.0f;

    for (int ch = 0; ch < 8; ch++) {
        if (ch) __syncthreads();          // previous compute done before overwrite
        load_conv(A, m0, ch * 64, smAh, smAl, tid);
        load_conv(W, n0, ch * 64, smBh, smBl, tid);
        __syncthreads();

#pragma unroll
        for (int ks = 0; ks < 4; ks++) {
            const uint32_t kb = ks * 32;  // 16 bf16 = 32 bytes
            uint32_t ah[4][4], al[4][4], bh[4][2], bl[4][2];
#pragma unroll
            for (int mi = 0; mi < 4; mi++)
                ldsm4(ah[mi], smb + (uint32_t)(m_w + mi * 16) * ROWB + aOff + kb);
#pragma unroll
            for (int ni = 0; ni < 4; ni++)
                ldsm2(bh[ni], smb + 2 * TILEB + (uint32_t)(n_w + ni * 8) * ROWB + bOff + kb);
            // term 1: Ah * Bh
#pragma unroll
            for (int mi = 0; mi < 4; mi++)
#pragma unroll
                for (int ni = 0; ni < 4; ni++) mma_bf16(c[mi][ni], ah[mi], bh[ni]);
            // term 2: Ah * Bl
#pragma unroll
            for (int ni = 0; ni < 4; ni++)
                ldsm2(bl[ni], smb + 3 * TILEB + (uint32_t)(n_w + ni * 8) * ROWB + bOff + kb);
#pragma unroll
            for (int mi = 0; mi < 4; mi++)
#pragma unroll
                for (int ni = 0; ni < 4; ni++) mma_bf16(c[mi][ni], ah[mi], bl[ni]);
            // term 3: Al * Bh
#pragma unroll
            for (int mi = 0; mi < 4; mi++)
                ldsm4(al[mi], smb + TILEB + (uint32_t)(m_w + mi * 16) * ROWB + aOff + kb);
#pragma unroll
            for (int mi = 0; mi < 4; mi++)
#pragma unroll
                for (int ni = 0; ni < 4; ni++) mma_bf16(c[mi][ni], al[mi], bh[ni]);
        }
    }

    // epilogue: lane holds D[r + {0,8}][col, col+1] per (mi, ni) tile
#pragma unroll
    for (int mi = 0; mi < 4; mi++) {
#pragma unroll
        for (int rr = 0; rr < 2; rr++) {
            const int r = m0 + m_w + mi * 16 + (lane >> 2) + rr * 8;
            int b = 0, tok = 0;
            if (MODE == 0) { b = r / NTOK; tok = r - b * NTOK; }
#pragma unroll
            for (int ni = 0; ni < 4; ni++) {
                const int n = n0 + n_w + ni * 8 + (lane & 3) * 2;   // even
                float v0 = c[mi][ni][rr * 2 + 0] + __ldg(bias + n);
                float v1 = c[mi][ni][rr * 2 + 1] + __ldg(bias + n + 1);
                if (MODE == 0) {
                    int s  = n >> 9;
                    int h  = (n >> 5) & 15;
                    int dd = n & 31;
                    float* dst = (s == 0) ? g_q : (s == 1) ? g_k : g_v;
                    if (s == 0) { v0 *= SCALE_Q; v1 *= SCALE_Q; }
                    size_t idx = (((size_t)b * HEADS + h) * NTOK + tok) * HD + dd;
                    *(float2*)(dst + idx) = make_float2(v0, v1);
                } else {
                    *(float2*)(Cout + (size_t)r * NPROJ + n) = make_float2(v0, v1);
                }
            }
        }
    }
}

// ---------------------------------------------------------------------------
// 3. attention: one CTA per (b,h); thread i owns query row i (i<49). (unchanged)
// ---------------------------------------------------------------------------
__global__ __launch_bounds__(64) void attn_kernel(const float* __restrict__ mask) {
    __shared__ __align__(16) float ks[NTOK * HD];
    __shared__ __align__(16) float vs[NTOK * HD];

    int bh = blockIdx.x;          // b*16 + h
    int b  = bh >> 4;
    int h  = bh & 15;
    int w  = b & 63;              // window index within image

    size_t base = (size_t)bh * (NTOK * HD);
    {
        const float4* kg = (const float4*)(g_k + base);
        const float4* vg = (const float4*)(g_v + base);
        float4* ks4 = (float4*)ks;
        float4* vs4 = (float4*)vs;
        for (int t = threadIdx.x; t < (NTOK * HD) / 4; t += 64) {
            ks4[t] = kg[t];
            vs4[t] = vg[t];
        }
    }
    __syncthreads();

    int i = threadIdx.x;
    if (i >= NTOK) return;

    unsigned long long q2[16];
    {
        const ulonglong2* qp = (const ulonglong2*)(g_q + base + (size_t)i * HD);
#pragma unroll
        for (int t = 0; t < 8; t++) {
            ulonglong2 u = qp[t];
            q2[2 * t]     = u.x;
            q2[2 * t + 1] = u.y;
        }
    }

    const float* bb = g_hbias + (h * (NTOK * NTOK) + i * NTOK);
    const float* mm = mask + ((size_t)w * NTOK + i) * NTOK;

    float s[NTOK];
#pragma unroll
    for (int j = 0; j < NTOK; j++) {
        const ulonglong2* kr = (const ulonglong2*)(ks + j * HD);
        unsigned long long a0 = 0, a1 = 0, a2 = 0, a3 = 0;
#pragma unroll
        for (int t = 0; t < 4; t++) {
            ulonglong2 k0 = kr[2 * t];
            ulonglong2 k1 = kr[2 * t + 1];
            a0 = ffma2(q2[4 * t + 0], k0.x, a0);
            a1 = ffma2(q2[4 * t + 1], k0.y, a1);
            a2 = ffma2(q2[4 * t + 2], k1.x, a2);
            a3 = ffma2(q2[4 * t + 3], k1.y, a3);
        }
        float r = (lo32(a0) + hi32(a0)) + (lo32(a1) + hi32(a1)) +
                  (lo32(a2) + hi32(a2)) + (lo32(a3) + hi32(a3));
        s[j] = r + __ldg(bb + j) + __ldg(mm + j);
    }

    float mx = s[0];
#pragma unroll
    for (int j = 1; j < NTOK; j++) mx = fmaxf(mx, s[j]);
    float sum = 0.0f;
#pragma unroll
    for (int j = 0; j < NTOK; j++) {
        float e = __expf(s[j] - mx);
        s[j] = e;
        sum += e;
    }
    float inv = 1.0f / sum;

    unsigned long long o2[16];
#pragma unroll
    for (int t = 0; t < 16; t++) o2[t] = 0ull;
#pragma unroll
    for (int j = 0; j < NTOK; j++) {
        unsigned long long pp = pack2(s[j], s[j]);
        const ulonglong2* vr = (const ulonglong2*)(vs + j * HD);
#pragma unroll
        for (int t = 0; t < 8; t++) {
            ulonglong2 vv = vr[t];
            o2[2 * t]     = ffma2(pp, vv.x, o2[2 * t]);
            o2[2 * t + 1] = ffma2(pp, vv.y, o2[2 * t + 1]);
        }
    }

    float* og = g_att + ((size_t)(b * NTOK + i)) * 512 + h * HD;
#pragma unroll
    for (int t = 0; t < 8; t++) {
        float4 f;
        f.x = lo32(o2[2 * t]) * inv;
        f.y = hi32(o2[2 * t]) * inv;
        f.z = lo32(o2[2 * t + 1]) * inv;
        f.w = hi32(o2[2 * t + 1]) * inv;
        *(float4*)(og + 4 * t) = f;
    }
}

// ---------------------------------------------------------------------------
extern "C" void kernel_launch(void* const* d_in, const int* in_sizes, int n_in,
                              void* d_out, int out_size) {
    const float* x          = (const float*)d_in[0];
    const float* w_qkv      = (const float*)d_in[1];
    const float* b_qkv      = (const float*)d_in[2];
    const float* w_proj     = (const float*)d_in[3];
    const float* b_proj     = (const float*)d_in[4];
    const float* bias_table = (const float*)d_in[5];
    const int*   rel_index  = (const int*)d_in[6];
    const float* mask       = (const float*)d_in[7];
    float* out = (float*)d_out;

    cudaFuncSetAttribute(gemm_mma<0>, cudaFuncAttributeMaxDynamicSharedMemorySize, SMEM_BYTES);
    cudaFuncSetAttribute(gemm_mma<1>, cudaFuncAttributeMaxDynamicSharedMemorySize, SMEM_BYTES);

    bias_kernel<<<(16 * 2401 + 255) / 256, 256>>>(bias_table, rel_index);
    gemm_mma<0><<<dim3(NQKV / 128, M_TOTAL / 128), 256, SMEM_BYTES>>>(x, w_qkv, b_qkv, nullptr);
    attn_kernel<<<2048 * 16, 64>>>(mask);
    gemm_mma<1><<<dim3(NPROJ / 128, M_TOTAL / 128), 256, SMEM_BYTES>>>(nullptr, w_proj, b_proj, out);
}